// round 16
// baseline (speedup 1.0000x reference)
#include <cuda_runtime.h>
#include <cuda_fp16.h>
#include <mma.h>
#include <cstdint>

using namespace nvcuda;

#define N_TOK 4096
#define DIM   512
#define HID   2048
#define NE    8
#define NPAIR (N_TOK * 2)

// GEMM tiling: CTA 128x64, BK=32, 128 threads (4 warps 2x2), warp tile 64x32
#define M_T 128
#define N_T 64
#define BK  32

// smem pitches (elements): A rows 40 (80B), B rows 72 (144B)
#define ALD 40
#define BLD 72
static constexpr int SA = 0;                 // 128*40*2 = 10240
#define SB_OFF 10240                          // 32*72*2  = 4608
static constexpr int STG  = 14848;           // one pipeline stage
static constexpr int NSTG = 3;
static constexpr int SMEM_DYN = NSTG * STG;  // 44544 B -> 4 CTAs/SM (178K)

// ---------------- scratch (static device memory; device-code access ONLY) ---
// NOTE: never pass these as kernel arguments from host — host code sees the
// host *shadow* symbol, not the device address (silent corruption via ATS).
__device__ __align__(256) __half g_xh[(size_t)N_TOK * DIM];
__device__ __align__(256) __half g_w1h[(size_t)NE * DIM * HID];
__device__ __align__(256) __half g_w2h[(size_t)NE * HID * DIM];
__device__ __align__(256) __half g_Hh[(size_t)NPAIR * HID];
__device__ __align__(256) float g_O[(size_t)NPAIR * DIM];
__device__ __align__(256) float g_pw[NPAIR];
__device__ __align__(256) int   g_list[NE * NPAIR];
__device__ int g_cnt[NE];

// ---------------- PTX helpers ------------------------------------------------
__device__ __forceinline__ uint32_t smem_u32(const void* p) {
    uint32_t a;
    asm("{ .reg .u64 t; cvta.to.shared.u64 t, %1; cvt.u32.u64 %0, t; }"
        : "=r"(a) : "l"(p));
    return a;
}
__device__ __forceinline__ void cpa16(uint32_t s, const void* g) {
    asm volatile("cp.async.cg.shared.global [%0], [%1], 16;"
                 :: "r"(s), "l"(g) : "memory");
}
__device__ __forceinline__ void cpa_commit() {
    asm volatile("cp.async.commit_group;" ::: "memory");
}
template<int N>
__device__ __forceinline__ void cpa_wait() {
    asm volatile("cp.async.wait_group %0;" :: "n"(N) : "memory");
}

// ---------------- aux kernels ------------------------------------------------
__global__ void k_zero(float* __restrict__ usage) {
    int t = threadIdx.x;
    if (t < NE) { g_cnt[t] = 0; usage[t] = 0.0f; }
}

// fused W1+W2 convert: fp32 -> fp16, one launch for both weight tensors
__global__ void k_split_w(const float* __restrict__ W1,
                          const float* __restrict__ W2) {
    constexpr int W_N4 = NE * DIM * HID / 4;
    int i = blockIdx.x * blockDim.x + threadIdx.x;
    const float* src; __half* dst; int j;
    if (i < W_N4)          { src = W1; dst = g_w1h; j = i; }
    else if (i < 2 * W_N4) { src = W2; dst = g_w2h; j = i - W_N4; }
    else return;
    float4 v = ((const float4*)src)[j];
    ((half2*)dst)[j * 2 + 0] = __floats2half2_rn(v.x, v.y);
    ((half2*)dst)[j * 2 + 1] = __floats2half2_rn(v.z, v.w);
}

// ---------------- fused gate + x-convert: one pass over x -------------------
__global__ void __launch_bounds__(128) k_gatesplit(
        const float* __restrict__ x,
        const float* __restrict__ Wg,
        const float* __restrict__ bg,
        float* __restrict__ usage) {
    __shared__ float wgt[NE][DIM + 4];          // transposed Wg, padded
    const int tid = threadIdx.x;
    for (int i = tid; i < DIM * NE; i += 128) {
        int d = i >> 3, e = i & 7;              // Wg is [d][e]
        wgt[e][d] = Wg[i];
    }
    __syncthreads();

    const int warp = tid >> 5, lane = tid & 31;
    const int n = blockIdx.x * 4 + warp;        // 4 warps per block
    const float4* xr = (const float4*)(x + (size_t)n * DIM);
    __half* hp = g_xh + (size_t)n * DIM;

    float p[NE];
#pragma unroll
    for (int e = 0; e < NE; e++) p[e] = 0.0f;

#pragma unroll
    for (int j = 0; j < 4; j++) {
        const int d4 = j * 32 + lane;           // float4 index in row (0..127)
        const int d0 = d4 * 4;
        float4 v = xr[d4];
        ((half2*)(hp + d0))[0] = __floats2half2_rn(v.x, v.y);
        ((half2*)(hp + d0))[1] = __floats2half2_rn(v.z, v.w);
#pragma unroll
        for (int e = 0; e < NE; e++) {
            const float4 w = *(const float4*)&wgt[e][d0];
            p[e] = fmaf(v.x, w.x, p[e]);
            p[e] = fmaf(v.y, w.y, p[e]);
            p[e] = fmaf(v.z, w.z, p[e]);
            p[e] = fmaf(v.w, w.w, p[e]);
        }
    }
#pragma unroll
    for (int o = 16; o; o >>= 1)
#pragma unroll
        for (int e = 0; e < NE; e++) p[e] += __shfl_xor_sync(0xffffffffu, p[e], o);

    if (lane == 0) {
#pragma unroll
        for (int e = 0; e < NE; e++) p[e] += bg[e];
        int i0 = 0;
#pragma unroll
        for (int e = 1; e < NE; e++) if (p[e] > p[i0]) i0 = e;
        int i1 = (i0 == 0) ? 1 : 0;
#pragma unroll
        for (int e = 0; e < NE; e++) if (e != i0 && p[e] > p[i1]) i1 = e;
        float w0 = 1.0f / (1.0f + expf(p[i1] - p[i0]));
        float w1 = 1.0f - w0;
        g_pw[2 * n + 0] = w0;
        g_pw[2 * n + 1] = w1;
        atomicAdd(&usage[i0], w0);
        atomicAdd(&usage[i1], w1);
        int q0 = atomicAdd(&g_cnt[i0], 1); g_list[i0 * NPAIR + q0] = 2 * n;
        int q1 = atomicAdd(&g_cnt[i1], 1); g_list[i1 * NPAIR + q1] = 2 * n + 1;
    }
}

// ---------------- grouped GEMM via wmma fp16 + 3-stage cp.async pipeline ----
// D[m,n] = sum_k A[m,k] * B[k,n] + bias[n]   (single-pass fp16, fp32 accum)
// A: gathered rows via g_list (row = pid>>ROWSH), K-major [*, KTOT]
// B: [E][KTOT][NTOT] row-major.  HALF_OUT: emit fp16 (fc1) else fp32 (fc2).
// Warp tile 64x32 (acc[4][2]) -> ~125 regs -> 4 CTAs/SM, 16 warps.
template<int KTOT, int NTOT, int ROWSH, bool HALF_OUT>
__device__ __forceinline__ void gemm_body(
        const __half* Amat, const __half* Bmat,
        const float* __restrict__ bias,
        __half* Oh, float* Ofp) {
    constexpr int NCH = KTOT / BK;
    extern __shared__ __align__(16) char sm[];

    const int e   = blockIdx.z;
    const int cnt = g_cnt[e];
    const int m0  = blockIdx.y * M_T;
    if (m0 >= cnt) return;
    const int n0  = blockIdx.x * N_T;
    const int tid  = threadIdx.x;
    const int wid  = tid >> 5;
    const int lane = tid & 31;
    const int wm = wid & 1;        // 2 warps along M: 64 rows each
    const int wn = wid >> 1;       // 2 warps along N: 32 cols each

    const uint32_t sb = smem_u32(sm);

    // ---- loader setup -------------------------------------------------------
    // A: 128 rows x 4 segs = 512 segs; thread owns tid + 128j (j=0..3)
    uint32_t dA[4], aoff[4];
#pragma unroll
    for (int j = 0; j < 4; j++) {
        const int s  = tid + 128 * j;
        const int ar = s >> 2, ac = (s & 3) * 16;
        int am = m0 + ar; if (am >= cnt) am = m0;       // duplicate; discarded
        aoff[j] = (uint32_t)((g_list[e * NPAIR + am] >> ROWSH) * (KTOT * 2)) + ac;
        dA[j]   = (uint32_t)(ar * (ALD * 2) + ac);
    }
    // B: 32 k-rows x 8 segs = 256 segs; thread owns tid + 128j (j=0..1)
    uint32_t dB[2], boff[2];
#pragma unroll
    for (int j = 0; j < 2; j++) {
        const int s  = tid + 128 * j;
        const int bk = s >> 3, bc = (s & 7) * 16;
        dB[j]   = (uint32_t)(bk * (BLD * 2) + bc);
        boff[j] = (uint32_t)(((e * KTOT + bk) * NTOT + n0) * 2 + bc);
    }
    const char* pA = (const char*)Amat;
    const char* pB = (const char*)Bmat;

    auto issue = [&](int c) {
        const uint32_t st = sb + (uint32_t)(c % NSTG) * STG;
        const uint32_t ga = (uint32_t)c * (BK * 2);        // A: +64B per chunk
        const uint32_t gb = (uint32_t)c * (BK * NTOT * 2); // B: +32 k-rows
#pragma unroll
        for (int j = 0; j < 4; j++)
            cpa16(st + SA + dA[j], pA + aoff[j] + ga);
#pragma unroll
        for (int j = 0; j < 2; j++)
            cpa16(st + SB_OFF + dB[j], pB + boff[j] + gb);
        cpa_commit();
    };

    wmma::fragment<wmma::accumulator, 16, 16, 16, float> acc[4][2];
#pragma unroll
    for (int mi = 0; mi < 4; mi++)
#pragma unroll
        for (int nj = 0; nj < 2; nj++) wmma::fill_fragment(acc[mi][nj], 0.0f);

    issue(0);
    issue(1);                                  // NCH >= 16 always
    for (int c = 0; c < NCH; c++) {
        if (c + 1 < NCH) cpa_wait<1>();        // stage c arrived
        else             cpa_wait<0>();
        __syncthreads();                       // ...and visible to all warps
        if (c + 2 < NCH) issue(c + 2);         // into stage (c-1)%3: safe

        const char* stg = sm + (size_t)(c % NSTG) * STG;
        const __half* sA  = (const __half*)(stg + SA);
        const __half* sBp = (const __half*)(stg + SB_OFF);
#pragma unroll
        for (int ks = 0; ks < 2; ks++) {
            // cache 2 B frags, reload A per mi (A loads: 4/ks, B: 2/ks)
            wmma::fragment<wmma::matrix_b, 16, 16, 16, __half,
                           wmma::row_major> bf[2];
#pragma unroll
            for (int nj = 0; nj < 2; nj++) {
                const int bo2 = (ks * 16) * BLD + wn * 32 + nj * 16;
                wmma::load_matrix_sync(bf[nj], sBp + bo2, BLD);
            }
#pragma unroll
            for (int mi = 0; mi < 4; mi++) {
                wmma::fragment<wmma::matrix_a, 16, 16, 16, __half,
                               wmma::row_major> af;
                const int ro = (wm * 64 + mi * 16) * ALD + ks * 16;
                wmma::load_matrix_sync(af, sA + ro, ALD);
#pragma unroll
                for (int nj = 0; nj < 2; nj++)
                    wmma::mma_sync(acc[mi][nj], af, bf[nj], acc[mi][nj]);
            }
        }
    }
    __syncthreads();                            // done with tiles; reuse as cs

    // ---- epilogue: per-warp 16x16 fp32 staging (pitch 20) ------------------
    float* cs = reinterpret_cast<float*>(sm + wid * (16 * 20 * 4));
    const int r  = lane >> 1;
    const int c0 = (lane & 1) * 8;
#pragma unroll
    for (int mi = 0; mi < 4; mi++) {
#pragma unroll
        for (int nj = 0; nj < 2; nj++) {
            wmma::store_matrix_sync(cs, acc[mi][nj], 20, wmma::mem_row_major);
            __syncwarp();
            const int m = m0 + wm * 64 + mi * 16 + r;
            if (m < cnt) {
                const int pid = g_list[e * NPAIR + m];
                const int nc  = n0 + wn * 32 + nj * 16 + c0;
                const float* bp = bias + (size_t)e * NTOT + nc;
                const float* cp = cs + r * 20 + c0;
                if (HALF_OUT) {
                    __half* op = Oh + (size_t)pid * NTOT + nc;
#pragma unroll
                    for (int p = 0; p < 4; p++) {
                        float v0 = cp[2 * p + 0] + bp[2 * p + 0];
                        float v1 = cp[2 * p + 1] + bp[2 * p + 1];
                        *(half2*)(op + 2 * p) = __floats2half2_rn(v0, v1);
                    }
                } else {
                    float* op = Ofp + (size_t)pid * NTOT + nc;
                    float4 w0, w1;
                    w0.x = cp[0] + bp[0]; w0.y = cp[1] + bp[1];
                    w0.z = cp[2] + bp[2]; w0.w = cp[3] + bp[3];
                    w1.x = cp[4] + bp[4]; w1.y = cp[5] + bp[5];
                    w1.z = cp[6] + bp[6]; w1.w = cp[7] + bp[7];
                    *(float4*)(op + 0) = w0;
                    *(float4*)(op + 4) = w1;
                }
            }
            __syncwarp();                       // before cs is overwritten
        }
    }
}

// Concrete wrappers: globals referenced from DEVICE code (correct addresses).
__global__ void __launch_bounds__(128, 4) k_fc1g(const float* __restrict__ b1) {
    gemm_body<DIM, HID, 1, true>(g_xh, g_w1h, b1, g_Hh, nullptr);
}
__global__ void __launch_bounds__(128, 4) k_fc2g(const float* __restrict__ b2) {
    gemm_body<HID, DIM, 0, false>(g_Hh, g_w2h, b2, nullptr, g_O);
}

// ---------------- combine ----------------------------------------------------
__global__ void k_comb(float* __restrict__ out) {
    int idx = blockIdx.x * blockDim.x + threadIdx.x;
    if (idx >= N_TOK * DIM / 4) return;
    int n  = idx / (DIM / 4);
    int d4 = idx % (DIM / 4);
    float w0 = g_pw[2 * n + 0];
    float w1 = g_pw[2 * n + 1];
    float4 a = *(const float4*)(g_O + (size_t)(2 * n + 0) * DIM + d4 * 4);
    float4 b = *(const float4*)(g_O + (size_t)(2 * n + 1) * DIM + d4 * 4);
    float4 r;
    r.x = w0 * a.x + w1 * b.x;
    r.y = w0 * a.y + w1 * b.y;
    r.z = w0 * a.z + w1 * b.z;
    r.w = w0 * a.w + w1 * b.w;
    *(float4*)(out + (size_t)idx * 4) = r;
}

// ---------------------------------------------------------------------------
extern "C" void kernel_launch(void* const* d_in, const int* in_sizes, int n_in,
                              void* d_out, int out_size) {
    const float* x  = (const float*)d_in[0];
    const float* Wg = (const float*)d_in[1];
    const float* bg = (const float*)d_in[2];
    const float* W1 = (const float*)d_in[3];
    const float* b1 = (const float*)d_in[4];
    const float* W2 = (const float*)d_in[5];
    const float* b2 = (const float*)d_in[6];
    float* out   = (float*)d_out;
    float* usage = out + (size_t)N_TOK * DIM;

    k_zero<<<1, 32>>>(usage);
    k_split_w<<<(2 * NE * DIM * HID / 4 + 255) / 256, 256>>>(W1, W2);
    k_gatesplit<<<N_TOK / 4, 128>>>(x, Wg, bg, usage);
    k_fc1g<<<dim3(HID / N_T, NPAIR / M_T, NE), 128, SMEM_DYN>>>(b1);
    k_fc2g<<<dim3(DIM / N_T, NPAIR / M_T, NE), 128, SMEM_DYN>>>(b2);
    k_comb<<<(N_TOK * DIM / 4) / 256, 256>>>(out);
}

// round 17
// speedup vs baseline: 1.2960x; 1.2960x over previous
#include <cuda_runtime.h>
#include <cuda_fp16.h>
#include <mma.h>
#include <cstdint>

using namespace nvcuda;

#define N_TOK 4096
#define DIM   512
#define HID   2048
#define NE    8
#define NPAIR (N_TOK * 2)

// GEMM tiling: CTA 128x128, BK=32, 128 threads (4 warps 2x2), warp tile 64x64
#define M_T 128
#define N_T 128
#define BK  32

// smem pitches (elements): A rows 40 (80B), B rows 136 (272B)
#define ALD 40
#define BLD 136
static constexpr int SA = 0;                 // 128*40*2 = 10240
#define SB_OFF 10240                          // 32*136*2 = 8704
static constexpr int STG  = 18944;           // one pipeline stage
static constexpr int NSTG = 3;
static constexpr int SMEM_DYN = NSTG * STG;  // 56832 B -> 2 CTAs/SM

// ---------------- scratch (static device memory; device-code access ONLY) ---
// NOTE: never pass these as kernel arguments from host — host code sees the
// host *shadow* symbol, not the device address (silent corruption via ATS).
__device__ __align__(256) __half g_xh[(size_t)N_TOK * DIM];
__device__ __align__(256) __half g_w1h[(size_t)NE * DIM * HID];
__device__ __align__(256) __half g_w2h[(size_t)NE * HID * DIM];
__device__ __align__(256) __half g_Hh[(size_t)NPAIR * HID];
__device__ __align__(256) float g_O[(size_t)NPAIR * DIM];
__device__ __align__(256) float g_pw[NPAIR];
__device__ __align__(256) int   g_list[NE * NPAIR];
__device__ int g_cnt[NE];

// ---------------- PTX helpers ------------------------------------------------
__device__ __forceinline__ uint32_t smem_u32(const void* p) {
    uint32_t a;
    asm("{ .reg .u64 t; cvta.to.shared.u64 t, %1; cvt.u32.u64 %0, t; }"
        : "=r"(a) : "l"(p));
    return a;
}
__device__ __forceinline__ void cpa16(uint32_t s, const void* g) {
    asm volatile("cp.async.cg.shared.global [%0], [%1], 16;"
                 :: "r"(s), "l"(g) : "memory");
}
__device__ __forceinline__ void cpa_commit() {
    asm volatile("cp.async.commit_group;" ::: "memory");
}
template<int N>
__device__ __forceinline__ void cpa_wait() {
    asm volatile("cp.async.wait_group %0;" :: "n"(N) : "memory");
}

// ---------------- aux kernels ------------------------------------------------
__global__ void k_zero(float* __restrict__ usage) {
    int t = threadIdx.x;
    if (t < NE) { g_cnt[t] = 0; usage[t] = 0.0f; }
}

__device__ __forceinline__ void cvt_body(const float* __restrict__ src,
                                         __half* dst, int n4) {
    int i = blockIdx.x * blockDim.x + threadIdx.x;
    if (i >= n4) return;
    float4 v = ((const float4*)src)[i];
    ((half2*)dst)[i * 2 + 0] = __floats2half2_rn(v.x, v.y);
    ((half2*)dst)[i * 2 + 1] = __floats2half2_rn(v.z, v.w);
}
__global__ void k_split_w1(const float* __restrict__ W1) {
    cvt_body(W1, g_w1h, NE * DIM * HID / 4);
}
__global__ void k_split_w2(const float* __restrict__ W2) {
    cvt_body(W2, g_w2h, NE * HID * DIM / 4);
}

// ---------------- fused gate + x-convert: one pass over x -------------------
__global__ void __launch_bounds__(128) k_gatesplit(
        const float* __restrict__ x,
        const float* __restrict__ Wg,
        const float* __restrict__ bg,
        float* __restrict__ usage) {
    __shared__ float wgt[NE][DIM + 4];          // transposed Wg, padded
    const int tid = threadIdx.x;
    for (int i = tid; i < DIM * NE; i += 128) {
        int d = i >> 3, e = i & 7;              // Wg is [d][e]
        wgt[e][d] = Wg[i];
    }
    __syncthreads();

    const int warp = tid >> 5, lane = tid & 31;
    const int n = blockIdx.x * 4 + warp;        // 4 warps per block
    const float4* xr = (const float4*)(x + (size_t)n * DIM);
    __half* hp = g_xh + (size_t)n * DIM;

    float p[NE];
#pragma unroll
    for (int e = 0; e < NE; e++) p[e] = 0.0f;

#pragma unroll
    for (int j = 0; j < 4; j++) {
        const int d4 = j * 32 + lane;           // float4 index in row (0..127)
        const int d0 = d4 * 4;
        float4 v = xr[d4];
        ((half2*)(hp + d0))[0] = __floats2half2_rn(v.x, v.y);
        ((half2*)(hp + d0))[1] = __floats2half2_rn(v.z, v.w);
#pragma unroll
        for (int e = 0; e < NE; e++) {
            const float4 w = *(const float4*)&wgt[e][d0];
            p[e] = fmaf(v.x, w.x, p[e]);
            p[e] = fmaf(v.y, w.y, p[e]);
            p[e] = fmaf(v.z, w.z, p[e]);
            p[e] = fmaf(v.w, w.w, p[e]);
        }
    }
#pragma unroll
    for (int o = 16; o; o >>= 1)
#pragma unroll
        for (int e = 0; e < NE; e++) p[e] += __shfl_xor_sync(0xffffffffu, p[e], o);

    if (lane == 0) {
#pragma unroll
        for (int e = 0; e < NE; e++) p[e] += bg[e];
        int i0 = 0;
#pragma unroll
        for (int e = 1; e < NE; e++) if (p[e] > p[i0]) i0 = e;
        int i1 = (i0 == 0) ? 1 : 0;
#pragma unroll
        for (int e = 0; e < NE; e++) if (e != i0 && p[e] > p[i1]) i1 = e;
        float w0 = 1.0f / (1.0f + expf(p[i1] - p[i0]));
        float w1 = 1.0f - w0;
        g_pw[2 * n + 0] = w0;
        g_pw[2 * n + 1] = w1;
        atomicAdd(&usage[i0], w0);
        atomicAdd(&usage[i1], w1);
        int q0 = atomicAdd(&g_cnt[i0], 1); g_list[i0 * NPAIR + q0] = 2 * n;
        int q1 = atomicAdd(&g_cnt[i1], 1); g_list[i1 * NPAIR + q1] = 2 * n + 1;
    }
}

// ---------------- grouped GEMM via wmma fp16 + 3-stage cp.async pipeline ----
// Exact R13 mainloop (best measured): wait -> sync -> compute -> issue(c+2).
template<int KTOT, int NTOT, int ROWSH, bool HALF_OUT>
__device__ __forceinline__ void gemm_body(
        const __half* Amat, const __half* Bmat,
        const float* __restrict__ bias,
        __half* Oh, float* Ofp) {
    constexpr int NCH = KTOT / BK;
    extern __shared__ __align__(16) char sm[];

    const int e   = blockIdx.z;
    const int cnt = g_cnt[e];
    const int m0  = blockIdx.y * M_T;
    if (m0 >= cnt) return;
    const int n0  = blockIdx.x * N_T;
    const int tid  = threadIdx.x;
    const int wid  = tid >> 5;
    const int lane = tid & 31;
    const int wm = wid & 1;        // 2 warps along M: 64 rows each
    const int wn = wid >> 1;       // 2 warps along N: 64 cols each

    const uint32_t sb = smem_u32(sm);

    // ---- loader setup: 128 threads, 4 segs each for A and for B ------------
    uint32_t dA[4], aoff[4];       // aoff includes the column-16 byte offset
    uint32_t dB[4], boff[4];
#pragma unroll
    for (int j = 0; j < 4; j++) {
        const int s  = tid + 128 * j;
        const int ar = s >> 2, ac = (s & 3) * 16;       // A: 128 rows x 4 segs
        int am = m0 + ar; if (am >= cnt) am = m0;       // duplicate; discarded
        aoff[j] = (uint32_t)((g_list[e * NPAIR + am] >> ROWSH) * (KTOT * 2)) + ac;
        dA[j]   = (uint32_t)(ar * (ALD * 2) + ac);
        const int bk = s >> 4, bc = (s & 15) * 16;      // B: 32 rows x 16 segs
        dB[j]   = (uint32_t)(bk * (BLD * 2) + bc);
        boff[j] = (uint32_t)(((e * KTOT + bk) * NTOT + n0) * 2 + bc);
    }
    const char* pA = (const char*)Amat;
    const char* pB = (const char*)Bmat;

    auto issue = [&](int c) {
        const uint32_t st = sb + (uint32_t)(c % NSTG) * STG;
        const uint32_t ga = (uint32_t)c * (BK * 2);        // A: +64B per chunk
        const uint32_t gb = (uint32_t)c * (BK * NTOT * 2); // B: +32 k-rows
#pragma unroll
        for (int j = 0; j < 4; j++) {
            cpa16(st + SA + dA[j], pA + aoff[j] + ga);
            cpa16(st + SB_OFF + dB[j], pB + boff[j] + gb);
        }
        cpa_commit();
    };

    wmma::fragment<wmma::accumulator, 16, 16, 16, float> acc[4][4];
#pragma unroll
    for (int mi = 0; mi < 4; mi++)
#pragma unroll
        for (int nj = 0; nj < 4; nj++) wmma::fill_fragment(acc[mi][nj], 0.0f);

    issue(0);
    issue(1);                                  // NCH >= 16 always
    for (int c = 0; c < NCH; c++) {
        if (c + 1 < NCH) cpa_wait<1>();        // stage c arrived
        else             cpa_wait<0>();
        __syncthreads();                       // ...and visible to all warps

        const char* stg = sm + (size_t)(c % NSTG) * STG;
        const __half* sA  = (const __half*)(stg + SA);
        const __half* sBp = (const __half*)(stg + SB_OFF);
#pragma unroll
        for (int ks = 0; ks < 2; ks++) {
            wmma::fragment<wmma::matrix_a, 16, 16, 16, __half,
                           wmma::row_major> af[4];
#pragma unroll
            for (int mi = 0; mi < 4; mi++) {
                const int ro = (wm * 64 + mi * 16) * ALD + ks * 16;
                wmma::load_matrix_sync(af[mi], sA + ro, ALD);
            }
#pragma unroll
            for (int nj = 0; nj < 4; nj++) {
                wmma::fragment<wmma::matrix_b, 16, 16, 16, __half,
                               wmma::row_major> bf;
                const int bo2 = (ks * 16) * BLD + wn * 64 + nj * 16;
                wmma::load_matrix_sync(bf, sBp + bo2, BLD);
#pragma unroll
                for (int mi = 0; mi < 4; mi++)
                    wmma::mma_sync(acc[mi][nj], af[mi], bf, acc[mi][nj]);
            }
        }
        if (c + 2 < NCH) issue(c + 2);         // into stage (c-1)%3: safe
    }
    __syncthreads();                            // done with tiles; reuse as cs

    // ---- epilogue: per-warp 16x16 fp32 staging (pitch 20) ------------------
    float* cs = reinterpret_cast<float*>(sm + wid * (16 * 20 * 4));
    const int r  = lane >> 1;
    const int c0 = (lane & 1) * 8;
#pragma unroll
    for (int mi = 0; mi < 4; mi++) {
#pragma unroll
        for (int nj = 0; nj < 4; nj++) {
            wmma::store_matrix_sync(cs, acc[mi][nj], 20, wmma::mem_row_major);
            __syncwarp();
            const int m = m0 + wm * 64 + mi * 16 + r;
            if (m < cnt) {
                const int pid = g_list[e * NPAIR + m];
                const int nc  = n0 + wn * 64 + nj * 16 + c0;
                const float* bp = bias + (size_t)e * NTOT + nc;
                const float* cp = cs + r * 20 + c0;
                if (HALF_OUT) {
                    __half* op = Oh + (size_t)pid * NTOT + nc;
#pragma unroll
                    for (int p = 0; p < 4; p++) {
                        float v0 = cp[2 * p + 0] + bp[2 * p + 0];
                        float v1 = cp[2 * p + 1] + bp[2 * p + 1];
                        *(half2*)(op + 2 * p) = __floats2half2_rn(v0, v1);
                    }
                } else {
                    float* op = Ofp + (size_t)pid * NTOT + nc;
                    float4 w0, w1;
                    w0.x = cp[0] + bp[0]; w0.y = cp[1] + bp[1];
                    w0.z = cp[2] + bp[2]; w0.w = cp[3] + bp[3];
                    w1.x = cp[4] + bp[4]; w1.y = cp[5] + bp[5];
                    w1.z = cp[6] + bp[6]; w1.w = cp[7] + bp[7];
                    *(float4*)(op + 0) = w0;
                    *(float4*)(op + 4) = w1;
                }
            }
            __syncwarp();                       // before cs is overwritten
        }
    }
}

// Concrete wrappers: globals referenced from DEVICE code (correct addresses).
__global__ void __launch_bounds__(128, 2) k_fc1g(const float* __restrict__ b1) {
    gemm_body<DIM, HID, 1, true>(g_xh, g_w1h, b1, g_Hh, nullptr);
}
__global__ void __launch_bounds__(128, 2) k_fc2g(const float* __restrict__ b2) {
    gemm_body<HID, DIM, 0, false>(g_Hh, g_w2h, b2, nullptr, g_O);
}

// ---------------- combine ----------------------------------------------------
__global__ void k_comb(float* __restrict__ out) {
    int idx = blockIdx.x * blockDim.x + threadIdx.x;
    if (idx >= N_TOK * DIM / 4) return;
    int n  = idx / (DIM / 4);
    int d4 = idx % (DIM / 4);
    float w0 = g_pw[2 * n + 0];
    float w1 = g_pw[2 * n + 1];
    float4 a = *(const float4*)(g_O + (size_t)(2 * n + 0) * DIM + d4 * 4);
    float4 b = *(const float4*)(g_O + (size_t)(2 * n + 1) * DIM + d4 * 4);
    float4 r;
    r.x = w0 * a.x + w1 * b.x;
    r.y = w0 * a.y + w1 * b.y;
    r.z = w0 * a.z + w1 * b.z;
    r.w = w0 * a.w + w1 * b.w;
    *(float4*)(out + (size_t)idx * 4) = r;
}

// ---------------------------------------------------------------------------
extern "C" void kernel_launch(void* const* d_in, const int* in_sizes, int n_in,
                              void* d_out, int out_size) {
    const float* x  = (const float*)d_in[0];
    const float* Wg = (const float*)d_in[1];
    const float* bg = (const float*)d_in[2];
    const float* W1 = (const float*)d_in[3];
    const float* b1 = (const float*)d_in[4];
    const float* W2 = (const float*)d_in[5];
    const float* b2 = (const float*)d_in[6];
    float* out   = (float*)d_out;
    float* usage = out + (size_t)N_TOK * DIM;

    // One-time handles (no device memory involved; identical work every call)
    static cudaStream_t s2 = nullptr;
    static cudaEvent_t evFork = nullptr, evW1 = nullptr, evW2 = nullptr;
    if (s2 == nullptr) {
        cudaStreamCreateWithFlags(&s2, cudaStreamNonBlocking);
        cudaEventCreateWithFlags(&evFork, cudaEventDisableTiming);
        cudaEventCreateWithFlags(&evW1, cudaEventDisableTiming);
        cudaEventCreateWithFlags(&evW2, cudaEventDisableTiming);
    }

    cudaFuncSetAttribute(k_fc1g, cudaFuncAttributeMaxDynamicSharedMemorySize,
                         SMEM_DYN);
    cudaFuncSetAttribute(k_fc2g, cudaFuncAttributeMaxDynamicSharedMemorySize,
                         SMEM_DYN);

    // fork side stream off the main (legacy) stream
    cudaEventRecord(evFork, 0);
    cudaStreamWaitEvent(s2, evFork, 0);

    // side stream: weight conversions
    k_split_w1<<<(NE * DIM * HID / 4 + 255) / 256, 256, 0, s2>>>(W1);
    cudaEventRecord(evW1, s2);
    k_split_w2<<<(NE * HID * DIM / 4 + 255) / 256, 256, 0, s2>>>(W2);
    cudaEventRecord(evW2, s2);

    // main stream: gate, then GEMMs (joining on the weight events)
    k_zero<<<1, 32>>>(usage);
    k_gatesplit<<<N_TOK / 4, 128>>>(x, Wg, bg, usage);
    cudaStreamWaitEvent(0, evW1, 0);
    k_fc1g<<<dim3(HID / N_T, NPAIR / M_T, NE), 128, SMEM_DYN>>>(b1);
    cudaStreamWaitEvent(0, evW2, 0);
    k_fc2g<<<dim3(DIM / N_T, NPAIR / M_T, NE), 128, SMEM_DYN>>>(b2);
    k_comb<<<(N_TOK * DIM / 4) / 256, 256>>>(out);
}